// round 1
// baseline (speedup 1.0000x reference)
#include <cuda_runtime.h>
#include <math.h>

// ---------------- problem constants ----------------
#define BB 8
#define NN 1024
#define DV 768
#define DS 512
#define FF 768
#define HH 12
#define DH 64
#define KG 1280        // Dv + Ds
#define ROWS (BB*NN)   // 8192
#define SCALE 0.125f   // dh^-0.5
#define EPS 1e-5f

// ---------------- scratch (device globals; no allocation allowed) ----------------
__device__ float g_q[BB*FF];
__device__ float g_gw[BB*HH*DV];      // scale * gv[d] * wqk[b,h,d]
__device__ float g_S1[BB*HH];         // sum_d gw
__device__ float g_S0[BB*HH];         // scale * sum_d bv[d]*wqk
__device__ float g_gsem[BB*DV];       // sem @ Wg[:,768:].T + bg
__device__ float g_mu[ROWS];
__device__ float g_rstd[ROWS];
__device__ float g_scores[BB*HH*NN];
__device__ float g_w[BB*HH*NN];       // attn * rstd
__device__ float g_t[BB*HH];          // sum_n attn*rstd*mu
#define NCHUNK 16
__device__ float g_vbarp[NCHUNK*BB*HH*DV];
__device__ float g_vbar[BB*HH*DV];
__device__ float g_ctx[BB*FF];
__device__ float g_att[BB*DV];

// ---------------- helpers ----------------
__device__ __forceinline__ float warp_sum(float v) {
#pragma unroll
    for (int o = 16; o > 0; o >>= 1) v += __shfl_down_sync(0xffffffffu, v, o);
    return v;
}
__device__ __forceinline__ float warp_max(float v) {
#pragma unroll
    for (int o = 16; o > 0; o >>= 1) v = fmaxf(v, __shfl_down_sync(0xffffffffu, v, o));
    return v;
}
// 256-thread block reduce (result broadcast to all threads)
__device__ __forceinline__ float block_sum256(float v, float* red) {
    int lane = threadIdx.x & 31, wid = threadIdx.x >> 5;
    __syncthreads();
    v = warp_sum(v);
    if (lane == 0) red[wid] = v;
    __syncthreads();
    if (wid == 0) {
        float x = (lane < 8) ? red[lane] : 0.f;
        x = warp_sum(x);
        if (lane == 0) red[0] = x;
    }
    __syncthreads();
    return red[0];
}
__device__ __forceinline__ float block_max256(float v, float* red) {
    int lane = threadIdx.x & 31, wid = threadIdx.x >> 5;
    __syncthreads();
    v = warp_max(v);
    if (lane == 0) red[wid] = v;
    __syncthreads();
    if (wid == 0) {
        float x = (lane < 8) ? red[lane] : -1e30f;
        x = warp_max(x);
        if (lane == 0) red[0] = x;
    }
    __syncthreads();
    return red[0];
}

// ---------------- K0a: semantic LN + q = sem_n @ Wq.T ----------------
__global__ __launch_bounds__(256) void k0a(const float* __restrict__ sem,
                                           const float* __restrict__ Wq,
                                           const float* __restrict__ gs,
                                           const float* __restrict__ bs) {
    int b = blockIdx.x;
    __shared__ float sm[DS];
    __shared__ float red[8];
    int tid = threadIdx.x, lane = tid & 31, wid = tid >> 5;
    float sum = 0.f, sq = 0.f;
    for (int i = tid; i < DS; i += 256) {
        float v = sem[b*DS + i];
        sm[i] = v; sum += v; sq += v*v;
    }
    sum = block_sum256(sum, red);
    sq  = block_sum256(sq, red);
    float mu = sum * (1.f/DS);
    float rstd = rsqrtf(sq * (1.f/DS) - mu*mu + EPS);
    for (int i = tid; i < DS; i += 256)
        sm[i] = (sm[i] - mu) * rstd * gs[i] + bs[i];
    __syncthreads();
    for (int f = wid; f < FF; f += 8) {
        float dot = 0.f;
        for (int s = lane; s < DS; s += 32) dot += sm[s] * Wq[(size_t)f*DS + s];
        dot = warp_sum(dot);
        if (lane == 0) g_q[b*FF + f] = dot;
    }
}

// ---------------- K0b: gw[b,h,:] = scale*gv*(q_h @ Wk_h), S1, S0 ----------------
__global__ __launch_bounds__(256) void k0b(const float* __restrict__ Wk,
                                           const float* __restrict__ gv,
                                           const float* __restrict__ bv) {
    int h = blockIdx.x, b = blockIdx.y;
    __shared__ float qh[DH];
    __shared__ float red[8];
    int tid = threadIdx.x;
    if (tid < DH) qh[tid] = g_q[b*FF + h*DH + tid];
    __syncthreads();
    float s1p = 0.f, s0p = 0.f;
    for (int d = tid; d < DV; d += 256) {
        float s = 0.f;
#pragma unroll 16
        for (int j = 0; j < DH; j++) s += qh[j] * Wk[(size_t)(h*DH + j)*DV + d];
        s *= SCALE;
        float gwv = gv[d] * s;
        g_gw[(b*HH + h)*DV + d] = gwv;
        s1p += gwv;
        s0p += bv[d] * s;
    }
    s1p = block_sum256(s1p, red);
    s0p = block_sum256(s0p, red);
    if (tid == 0) { g_S1[b*HH + h] = s1p; g_S0[b*HH + h] = s0p; }
}

// ---------------- K0c: gsem[b,:] = sem @ Wg[:,768:].T + bg ----------------
__global__ __launch_bounds__(256) void k0c(const float* __restrict__ sem,
                                           const float* __restrict__ Wg,
                                           const float* __restrict__ bg) {
    int b = blockIdx.x;
    __shared__ float sm[DS];
    int tid = threadIdx.x, lane = tid & 31, wid = tid >> 5;
    for (int i = tid; i < DS; i += 256) sm[i] = sem[b*DS + i];
    __syncthreads();
    for (int dv = wid; dv < DV; dv += 8) {
        float dot = 0.f;
        for (int s = lane; s < DS; s += 32) dot += sm[s] * Wg[(size_t)dv*KG + DV + s];
        dot = warp_sum(dot);
        if (lane == 0) g_gsem[b*DV + dv] = dot + bg[dv];
    }
}

// ---------------- K1: row stats + scores (8 rows per block) ----------------
__global__ __launch_bounds__(256) void k1(const float* __restrict__ vis) {
    __shared__ float gw_s[HH*DV];   // 36 KB
    __shared__ float xs[DV];
    __shared__ float red[8];
    __shared__ float s1[HH], s0[HH];
    int tid = threadIdx.x, lane = tid & 31, wid = tid >> 5;
    int row0 = blockIdx.x * 8;
    int b = row0 >> 10;
    for (int i = tid; i < HH*DV; i += 256) gw_s[i] = g_gw[b*HH*DV + i];
    if (tid < HH) { s1[tid] = g_S1[b*HH + tid]; s0[tid] = g_S0[b*HH + tid]; }
    __syncthreads();
    for (int r = 0; r < 8; r++) {
        int row = row0 + r;
        const float* x = vis + (size_t)row * DV;
        float sum = 0.f, sq = 0.f;
        for (int i = tid; i < DV; i += 256) {
            float v = x[i];
            xs[i] = v; sum += v; sq += v*v;
        }
        sum = block_sum256(sum, red);
        sq  = block_sum256(sq, red);
        float mu = sum * (1.f/DV);
        float rstd = rsqrtf(sq * (1.f/DV) - mu*mu + EPS);
        if (tid == 0) { g_mu[row] = mu; g_rstd[row] = rstd; }
        for (int h = wid; h < HH; h += 8) {
            float dot = 0.f;
            for (int d = lane; d < DV; d += 32) dot += xs[d] * gw_s[h*DV + d];
            dot = warp_sum(dot);
            if (lane == 0) {
                int n = row & (NN - 1);
                g_scores[(b*HH + h)*NN + n] = rstd * (dot - mu*s1[h]) + s0[h];
            }
        }
        __syncthreads();
    }
}

// ---------------- K2: softmax over n; w = attn*rstd, t = sum attn*rstd*mu ----------------
__global__ __launch_bounds__(256) void k2() {
    int bh = blockIdx.x;
    int b = bh / HH;
    __shared__ float red[8];
    int tid = threadIdx.x;
    float loc[4];
    float mx = -1e30f;
#pragma unroll
    for (int i = 0; i < 4; i++) {
        loc[i] = g_scores[bh*NN + tid + i*256];
        mx = fmaxf(mx, loc[i]);
    }
    mx = block_max256(mx, red);
    float s = 0.f;
#pragma unroll
    for (int i = 0; i < 4; i++) { loc[i] = expf(loc[i] - mx); s += loc[i]; }
    s = block_sum256(s, red);
    float inv = 1.f / s;
    float tp = 0.f;
#pragma unroll
    for (int i = 0; i < 4; i++) {
        int n = tid + i*256;
        float a = loc[i] * inv;
        float rs = g_rstd[b*NN + n];
        float w = a * rs;
        g_w[bh*NN + n] = w;
        tp += w * g_mu[b*NN + n];
    }
    tp = block_sum256(tp, red);
    if (tid == 0) g_t[bh] = tp;
}

// ---------------- K3: per-chunk partial vbar (deterministic, no atomics) ----------------
__global__ __launch_bounds__(768) void k3(const float* __restrict__ vis) {
    int chunk = blockIdx.x;     // 16 chunks of 64 tokens
    int b = blockIdx.y;
    int d = threadIdx.x;        // 768 threads = one per feature
    __shared__ float ws[HH][64];
    int n0 = chunk * 64;
    for (int i = d; i < HH*64; i += 768) {
        int h = i >> 6, j = i & 63;
        ws[h][j] = g_w[(b*HH + h)*NN + n0 + j];
    }
    __syncthreads();
    float acc[HH];
#pragma unroll
    for (int h = 0; h < HH; h++) acc[h] = 0.f;
    const float* base = vis + ((size_t)(b << 10) + n0) * DV + d;
    for (int j = 0; j < 64; j++) {
        float x = base[(size_t)j * DV];
#pragma unroll
        for (int h = 0; h < HH; h++) acc[h] += ws[h][j] * x;
    }
#pragma unroll
    for (int h = 0; h < HH; h++)
        g_vbarp[(size_t)chunk*(BB*HH*DV) + (b*HH + h)*DV + d] = acc[h];
}

// ---------------- K3b: reduce chunks ----------------
__global__ __launch_bounds__(1024) void k3b() {
    int i = blockIdx.x * 1024 + threadIdx.x;   // 72 blocks * 1024 = 73728
    float s = 0.f;
#pragma unroll
    for (int c = 0; c < NCHUNK; c++) s += g_vbarp[(size_t)c*(BB*HH*DV) + i];
    g_vbar[i] = s;
}

// ---------------- K4a: ctx[b,f] = u[b,h,:] @ Wv[f,:] ----------------
__global__ __launch_bounds__(256) void k4a(const float* __restrict__ Wv,
                                           const float* __restrict__ gv,
                                           const float* __restrict__ bv) {
    int h = blockIdx.x, b = blockIdx.y;
    __shared__ float u[DV];
    int tid = threadIdx.x, lane = tid & 31, wid = tid >> 5;
    float t = g_t[b*HH + h];
    for (int d = tid; d < DV; d += 256)
        u[d] = gv[d] * (g_vbar[(b*HH + h)*DV + d] - t) + bv[d];
    __syncthreads();
    for (int j = wid; j < DH; j += 8) {
        int f = h*DH + j;
        float dot = 0.f;
        for (int d = lane; d < DV; d += 32) dot += u[d] * Wv[(size_t)f*DV + d];
        dot = warp_sum(dot);
        if (lane == 0) g_ctx[b*FF + f] = dot;
    }
}

// ---------------- K4b: attended[b,:] = ctx @ Wo.T + bo ----------------
__global__ __launch_bounds__(256) void k4b(const float* __restrict__ Wo,
                                           const float* __restrict__ bo) {
    int b = blockIdx.x;
    __shared__ float c[FF];
    int tid = threadIdx.x, lane = tid & 31, wid = tid >> 5;
    for (int i = tid; i < FF; i += 256) c[i] = g_ctx[b*FF + i];
    __syncthreads();
    for (int dv = wid; dv < DV; dv += 8) {
        float dot = 0.f;
        for (int f = lane; f < FF; f += 32) dot += c[f] * Wo[(size_t)dv*FF + f];
        dot = warp_sum(dot);
        if (lane == 0) g_att[b*DV + dv] = dot + bo[dv];
    }
}

// ---------------- K5: gate GEMM + fused sigmoid/residual epilogue ----------------
// out[r,c] = A[r,c] + sigmoid( sum_k A[r,k]*Wg[c,k] + gsem[b,c] ) * att[b,c]
__global__ __launch_bounds__(256) void k5(const float* __restrict__ A,
                                          const float* __restrict__ Wg,
                                          float* __restrict__ out) {
    __shared__ float As[2][8][128];
    __shared__ float Bs[2][8][128];
    int rowBase = blockIdx.x * 128;
    int colBase = blockIdx.y * 128;
    int tid = threadIdx.x;
    int tx = tid & 15, ty = tid >> 4;
    int lr = tid >> 1;
    int lk = (tid & 1) * 4;
    const float* Aptr = A  + (size_t)(rowBase + lr)*DV + lk;
    const float* Bptr = Wg + (size_t)(colBase + lr)*KG + lk;

    float acc[8][8];
#pragma unroll
    for (int i = 0; i < 8; i++)
#pragma unroll
        for (int j = 0; j < 8; j++) acc[i][j] = 0.f;

    // prologue
    {
        float4 a4 = *(const float4*)Aptr;
        float4 b4 = *(const float4*)Bptr;
        As[0][lk+0][lr] = a4.x; As[0][lk+1][lr] = a4.y;
        As[0][lk+2][lr] = a4.z; As[0][lk+3][lr] = a4.w;
        Bs[0][lk+0][lr] = b4.x; Bs[0][lk+1][lr] = b4.y;
        Bs[0][lk+2][lr] = b4.z; Bs[0][lk+3][lr] = b4.w;
    }
    __syncthreads();

    int buf = 0;
    const int NKT = DV / 8;   // 96
    for (int kt = 0; kt < NKT; kt++) {
        float4 na, nb;
        if (kt < NKT - 1) {
            na = *(const float4*)(Aptr + (kt+1)*8);
            nb = *(const float4*)(Bptr + (kt+1)*8);
        }
#pragma unroll
        for (int k = 0; k < 8; k++) {
            float a[8], b[8];
#pragma unroll
            for (int i = 0; i < 8; i++) a[i] = As[buf][k][ty*8 + i];
#pragma unroll
            for (int j = 0; j < 8; j++) b[j] = Bs[buf][k][tx*8 + j];
#pragma unroll
            for (int i = 0; i < 8; i++)
#pragma unroll
                for (int j = 0; j < 8; j++) acc[i][j] += a[i] * b[j];
        }
        if (kt < NKT - 1) {
            buf ^= 1;
            As[buf][lk+0][lr] = na.x; As[buf][lk+1][lr] = na.y;
            As[buf][lk+2][lr] = na.z; As[buf][lk+3][lr] = na.w;
            Bs[buf][lk+0][lr] = nb.x; Bs[buf][lk+1][lr] = nb.y;
            Bs[buf][lk+2][lr] = nb.z; Bs[buf][lk+3][lr] = nb.w;
            __syncthreads();
        }
    }

    // epilogue
#pragma unroll
    for (int i = 0; i < 8; i++) {
        int r = rowBase + ty*8 + i;
        int bb = r >> 10;
        const float* gs = g_gsem + bb*DV;
        const float* at = g_att + bb*DV;
#pragma unroll
        for (int j4 = 0; j4 < 8; j4 += 4) {
            int c = colBase + tx*8 + j4;
            float4 av = *(const float4*)(A + (size_t)r*DV + c);
            float4 o;
            o.x = av.x + at[c+0] * (1.f / (1.f + __expf(-(acc[i][j4+0] + gs[c+0]))));
            o.y = av.y + at[c+1] * (1.f / (1.f + __expf(-(acc[i][j4+1] + gs[c+1]))));
            o.z = av.z + at[c+2] * (1.f / (1.f + __expf(-(acc[i][j4+2] + gs[c+2]))));
            o.w = av.w + at[c+3] * (1.f / (1.f + __expf(-(acc[i][j4+3] + gs[c+3]))));
            *(float4*)(out + (size_t)r*DV + c) = o;
        }
    }
}

// ---------------- launcher ----------------
extern "C" void kernel_launch(void* const* d_in, const int* in_sizes, int n_in,
                              void* d_out, int out_size) {
    const float* visual   = (const float*)d_in[0];
    const float* semantic = (const float*)d_in[1];
    const float* Wq = (const float*)d_in[2];
    const float* Wk = (const float*)d_in[3];
    const float* Wv = (const float*)d_in[4];
    const float* Wo = (const float*)d_in[5];
    const float* bo = (const float*)d_in[6];
    const float* Wg = (const float*)d_in[7];
    const float* bg = (const float*)d_in[8];
    const float* gv = (const float*)d_in[9];
    const float* bv = (const float*)d_in[10];
    const float* gs = (const float*)d_in[11];
    const float* bs = (const float*)d_in[12];
    float* out = (float*)d_out;

    k0a<<<BB, 256>>>(semantic, Wq, gs, bs);
    k0b<<<dim3(HH, BB), 256>>>(Wk, gv, bv);
    k0c<<<BB, 256>>>(semantic, Wg, bg);
    k1<<<ROWS/8, 256>>>(visual);
    k2<<<BB*HH, 256>>>();
    k3<<<dim3(NCHUNK, BB), 768>>>(visual);
    k3b<<<(BB*HH*DV)/1024, 1024>>>();
    k4a<<<dim3(HH, BB), 256>>>(Wv, gv, bv);
    k4b<<<BB, 256>>>(Wo, bo);
    k5<<<dim3(ROWS/128, DV/128), 256>>>(visual, Wg, out);
}